// round 9
// baseline (speedup 1.0000x reference)
#include <cuda_runtime.h>
#include <math.h>

// ---------------- problem dims ----------------
#define BSZ 256
#define TT  128
#define FF  512
#define HH  1024
#define G4  4096

// ---------------- GEMM tiling: 64x128 CTA tile, 256 threads, 4x8/thread ----
#define BMT 64
#define BNT 128
#define BKT 16

// ---------------- scratch (device globals) ----------------
__device__ float g_xproj[(size_t)BSZ * TT * G4]; // [B*T, 4H]
__device__ float g_gbuf[BSZ * G4];               // per-step gates
__device__ float g_pf[BSZ * HH];
__device__ float g_pi[BSZ * HH];
__device__ float g_h[BSZ * HH];
__device__ float g_c[BSZ * HH];

__device__ __forceinline__ float sigm(float v) { return 1.0f / (1.0f + expf(-v)); }

// ---------------- GEMM core ----------------
// C(64x128) = A[mbase.., :K] * B[:K, nbase..]
// A row-major [M, lda]; B row-major [K, ldb]. Double-buffered smem.
// sA layout: [buf][k][m]  (flat: buf*1024 + k*64 + m)
// sB layout: [buf][k][n]  (flat: buf*2048 + k*128 + n)
__device__ __forceinline__ void gemm_core(
    const float* __restrict__ A, int lda,
    const float* __restrict__ B, int ldb,
    int K, int mbase, int nbase,
    float* sA, float* sB, float acc[4][8])
{
    const int tid = threadIdx.x;
    const int tx = tid & 15;          // output col group (8 cols)
    const int ty = tid >> 4;          // output row group (4 rows)
    const int ar  = tid & 63;         // A loader: row 0..63
    const int ak4 = (tid >> 6) * 4;   // A loader: k offset 0,4,8,12

    const int nkc = K / BKT;

    // ---- preload chunk 0 into buffer 0 ----
    {
        float4 av = *(const float4*)&A[(size_t)(mbase + ar) * lda + ak4];
        sA[(ak4 + 0) * 64 + ar] = av.x;
        sA[(ak4 + 1) * 64 + ar] = av.y;
        sA[(ak4 + 2) * 64 + ar] = av.z;
        sA[(ak4 + 3) * 64 + ar] = av.w;
#pragma unroll
        for (int j = 0; j < 2; j++) {
            int e = tid + j * 256;
            int bk = e >> 5, bn4 = (e & 31) * 4;
            *(float4*)&sB[bk * 128 + bn4] =
                *(const float4*)&B[(size_t)bk * ldb + nbase + bn4];
        }
    }
    __syncthreads();

    for (int kc = 0; kc < nkc; kc++) {
        const int cur = kc & 1;
        const float* sAc = sA + cur * (BKT * 64);
        const float* sBc = sB + cur * (BKT * 128);

        // ---- issue next chunk's loads into the other buffer ----
        if (kc + 1 < nkc) {
            const int kb = (kc + 1) * BKT;
            float* sAn = sA + (cur ^ 1) * (BKT * 64);
            float* sBn = sB + (cur ^ 1) * (BKT * 128);
            float4 av = *(const float4*)&A[(size_t)(mbase + ar) * lda + kb + ak4];
            sAn[(ak4 + 0) * 64 + ar] = av.x;
            sAn[(ak4 + 1) * 64 + ar] = av.y;
            sAn[(ak4 + 2) * 64 + ar] = av.z;
            sAn[(ak4 + 3) * 64 + ar] = av.w;
#pragma unroll
            for (int j = 0; j < 2; j++) {
                int e = tid + j * 256;
                int bk = e >> 5, bn4 = (e & 31) * 4;
                *(float4*)&sBn[bk * 128 + bn4] =
                    *(const float4*)&B[(size_t)(kb + bk) * ldb + nbase + bn4];
            }
        }

        // ---- compute on current buffer ----
#pragma unroll
        for (int k = 0; k < BKT; k++) {
            float a0 = sAc[k * 64 + ty * 4 + 0];
            float a1 = sAc[k * 64 + ty * 4 + 1];
            float a2 = sAc[k * 64 + ty * 4 + 2];
            float a3 = sAc[k * 64 + ty * 4 + 3];
            float4 b0 = *(const float4*)&sBc[k * 128 + tx * 8];
            float4 b1 = *(const float4*)&sBc[k * 128 + tx * 8 + 4];
            acc[0][0] += a0 * b0.x; acc[0][1] += a0 * b0.y; acc[0][2] += a0 * b0.z; acc[0][3] += a0 * b0.w;
            acc[0][4] += a0 * b1.x; acc[0][5] += a0 * b1.y; acc[0][6] += a0 * b1.z; acc[0][7] += a0 * b1.w;
            acc[1][0] += a1 * b0.x; acc[1][1] += a1 * b0.y; acc[1][2] += a1 * b0.z; acc[1][3] += a1 * b0.w;
            acc[1][4] += a1 * b1.x; acc[1][5] += a1 * b1.y; acc[1][6] += a1 * b1.z; acc[1][7] += a1 * b1.w;
            acc[2][0] += a2 * b0.x; acc[2][1] += a2 * b0.y; acc[2][2] += a2 * b0.z; acc[2][3] += a2 * b0.w;
            acc[2][4] += a2 * b1.x; acc[2][5] += a2 * b1.y; acc[2][6] += a2 * b1.z; acc[2][7] += a2 * b1.w;
            acc[3][0] += a3 * b0.x; acc[3][1] += a3 * b0.y; acc[3][2] += a3 * b0.z; acc[3][3] += a3 * b0.w;
            acc[3][4] += a3 * b1.x; acc[3][5] += a3 * b1.y; acc[3][6] += a3 * b1.z; acc[3][7] += a3 * b1.w;
        }
        __syncthreads();
    }
}

#define GEMM_SMEM() \
    __shared__ float sA[2 * BKT * 64]; \
    __shared__ float sB[2 * BKT * 128]; \
    float acc[4][8] = {}; \
    const int tx = threadIdx.x & 15; \
    const int ty = threadIdx.x >> 4;

// ---------------- kernels ----------------
__global__ void k_init()
{
    int idx = blockIdx.x * blockDim.x + threadIdx.x;
    if (idx < BSZ * HH) { g_h[idx] = 0.0f; g_c[idx] = 0.0f; }
}

// x_proj = x @ W_x + b    (M=32768, K=512, N=4096); grid (32, 512)
__global__ void k_xproj(const float* __restrict__ x,
                        const float* __restrict__ Wx,
                        const float* __restrict__ bias)
{
    const int mbase = blockIdx.y * BMT, nbase = blockIdx.x * BNT;
    GEMM_SMEM();
    gemm_core(x, FF, Wx, G4, FF, mbase, nbase, sA, sB, acc);

    const int cc = nbase + tx * 8;
    float4 bb0 = *(const float4*)&bias[cc];
    float4 bb1 = *(const float4*)&bias[cc + 4];
#pragma unroll
    for (int i = 0; i < 4; i++) {
        size_t row = (size_t)mbase + ty * 4 + i;
        float4 v0 = make_float4(acc[i][0] + bb0.x, acc[i][1] + bb0.y,
                                acc[i][2] + bb0.z, acc[i][3] + bb0.w);
        float4 v1 = make_float4(acc[i][4] + bb1.x, acc[i][5] + bb1.y,
                                acc[i][6] + bb1.z, acc[i][7] + bb1.w);
        *(float4*)&g_xproj[row * G4 + cc] = v0;
        *(float4*)&g_xproj[row * G4 + cc + 4] = v1;
    }
}

// phase A: z0: gbuf = xp_t + h@R_h (N=4096); z1: pf = c@P_f; z2: pi = c@P_i (N=1024)
// grid (32, 4, 3)
__global__ void k_phaseA(const float* __restrict__ Rh,
                         const float* __restrict__ Pf,
                         const float* __restrict__ Pi,
                         int t)
{
    const int z = blockIdx.z;
    if (z > 0 && blockIdx.x >= 8) return;

    const int mbase = blockIdx.y * BMT, nbase = blockIdx.x * BNT;
    GEMM_SMEM();

    if (z == 0)      gemm_core(g_h, HH, Rh, G4, HH, mbase, nbase, sA, sB, acc);
    else if (z == 1) gemm_core(g_c, HH, Pf, HH, HH, mbase, nbase, sA, sB, acc);
    else             gemm_core(g_c, HH, Pi, HH, HH, mbase, nbase, sA, sB, acc);

    const int cc = nbase + tx * 8;
#pragma unroll
    for (int i = 0; i < 4; i++) {
        size_t row = (size_t)mbase + ty * 4 + i;
        if (z == 0) {
            size_t xb = (row * TT + t) * (size_t)G4 + cc;
            float4 x0 = *(const float4*)&g_xproj[xb];
            float4 x1 = *(const float4*)&g_xproj[xb + 4];
            float4 v0 = make_float4(acc[i][0] + x0.x, acc[i][1] + x0.y,
                                    acc[i][2] + x0.z, acc[i][3] + x0.w);
            float4 v1 = make_float4(acc[i][4] + x1.x, acc[i][5] + x1.y,
                                    acc[i][6] + x1.z, acc[i][7] + x1.w);
            *(float4*)&g_gbuf[row * G4 + cc] = v0;
            *(float4*)&g_gbuf[row * G4 + cc + 4] = v1;
        } else {
            float* outp = (z == 1) ? g_pf : g_pi;
            float4 v0 = make_float4(acc[i][0], acc[i][1], acc[i][2], acc[i][3]);
            float4 v1 = make_float4(acc[i][4], acc[i][5], acc[i][6], acc[i][7]);
            *(float4*)&outp[row * HH + cc] = v0;
            *(float4*)&outp[row * HH + cc + 4] = v1;
        }
    }
}

// cell update
__global__ void k_cell()
{
    int idx = blockIdx.x * blockDim.x + threadIdx.x;
    if (idx >= BSZ * HH) return;
    int b = idx >> 10, j = idx & 1023;
    const float* gr = g_gbuf + (size_t)b * G4;
    float f = sigm(gr[j] + g_pf[idx]);
    float i = sigm(gr[HH + j] + g_pi[idx]);
    float ct = tanhf(gr[2 * HH + j]);
    g_c[idx] = g_c[idx] * f + ct * i;
}

// phase B: po = c@P_o ; h = tanh(c) * sigm(go + po) ; grid (8, 4)
__global__ void k_phaseB(const float* __restrict__ Po,
                         float* __restrict__ dout, int last)
{
    const int mbase = blockIdx.y * BMT, nbase = blockIdx.x * BNT;
    GEMM_SMEM();
    gemm_core(g_c, HH, Po, HH, HH, mbase, nbase, sA, sB, acc);

    const int cc = nbase + tx * 8;
#pragma unroll
    for (int i = 0; i < 4; i++) {
        size_t row = (size_t)mbase + ty * 4 + i;
        float4 c0 = *(const float4*)&g_c[row * HH + cc];
        float4 c1 = *(const float4*)&g_c[row * HH + cc + 4];
        float4 o0 = *(const float4*)&g_gbuf[row * G4 + 3 * HH + cc];
        float4 o1 = *(const float4*)&g_gbuf[row * G4 + 3 * HH + cc + 4];
        float4 v0, v1;
        v0.x = tanhf(c0.x) * sigm(o0.x + acc[i][0]);
        v0.y = tanhf(c0.y) * sigm(o0.y + acc[i][1]);
        v0.z = tanhf(c0.z) * sigm(o0.z + acc[i][2]);
        v0.w = tanhf(c0.w) * sigm(o0.w + acc[i][3]);
        v1.x = tanhf(c1.x) * sigm(o1.x + acc[i][4]);
        v1.y = tanhf(c1.y) * sigm(o1.y + acc[i][5]);
        v1.z = tanhf(c1.z) * sigm(o1.z + acc[i][6]);
        v1.w = tanhf(c1.w) * sigm(o1.w + acc[i][7]);
        *(float4*)&g_h[row * HH + cc] = v0;
        *(float4*)&g_h[row * HH + cc + 4] = v1;
        if (last) {
            *(float4*)&dout[row * HH + cc] = v0;
            *(float4*)&dout[row * HH + cc + 4] = v1;
        }
    }
}

// ---------------- launch ----------------
extern "C" void kernel_launch(void* const* d_in, const int* in_sizes, int n_in,
                              void* d_out, int out_size)
{
    const float* x  = (const float*)d_in[0];
    const float* Wx = (const float*)d_in[1];
    const float* b  = (const float*)d_in[2];
    const float* Rh = (const float*)d_in[3];
    const float* Pf = (const float*)d_in[4];
    const float* Pi = (const float*)d_in[5];
    const float* Po = (const float*)d_in[6];
    float* out = (float*)d_out;
    (void)in_sizes; (void)n_in; (void)out_size;

    k_init<<<(BSZ * HH + 511) / 512, 512>>>();

    k_xproj<<<dim3(G4 / BNT, (BSZ * TT) / BMT), 256>>>(x, Wx, b);

    for (int t = 0; t < TT; t++) {
        k_phaseA<<<dim3(G4 / BNT, BSZ / BMT, 3), 256>>>(Rh, Pf, Pi, t);
        k_cell<<<(BSZ * HH + 511) / 512, 512>>>();
        k_phaseB<<<dim3(HH / BNT, BSZ / BMT), 256>>>(Po, out, (t == TT - 1) ? 1 : 0);
    }
}

// round 10
// speedup vs baseline: 1.3796x; 1.3796x over previous
#include <cuda_runtime.h>
#include <math.h>

// ---------------- problem dims ----------------
#define BSZ 256
#define TT  128
#define FF  512
#define HH  1024
#define G4  4096

// ---------------- GEMM tiling: 128x64 CTA tile, 256 threads, 8x4/thread ----
#define BMT 128
#define BNT 64
#define BKT 16

// ---------------- scratch (device globals) ----------------
__device__ float g_xproj[(size_t)BSZ * TT * G4]; // [B*T, 4H]
__device__ float g_gbuf[BSZ * G4];               // per-step gates
__device__ float g_pf[BSZ * HH];
__device__ float g_pi[BSZ * HH];
__device__ float g_h[BSZ * HH];
__device__ float g_c[BSZ * HH];

__device__ __forceinline__ float sigm(float v) { return 1.0f / (1.0f + expf(-v)); }

// ---------------- GEMM core (register-staged double buffering) ----------------
// C(128x64) = A[mbase.., :K] * B[:K, nbase..]
// A row-major [M, lda]; B row-major [K, ldb].
// sA: [buf][k][128] (A stored k-major/transposed), sB: [buf][k][64].
// Pipeline: LDG(next)->regs ; FFMA(cur) ; STS(regs->next buf) ; ONE sync.
__device__ __forceinline__ void gemm_core(
    const float* __restrict__ A, int lda,
    const float* __restrict__ B, int ldb,
    int K, int mbase, int nbase,
    float* sA, float* sB, float acc[8][4])
{
    const int tid = threadIdx.x;
    const int tx = tid & 15;          // output col group (4 cols)
    const int ty = tid >> 4;          // output row group (8 rows)

    // A loader: two float4 per thread per chunk.
    //   e0 = tid      -> r = tid & 127, kq0 = tid >> 7      (0 or 1)
    //   e1 = tid+256  -> same r,        kq1 = kq0 + 2       (2 or 3)
    const int ar  = tid & 127;
    const int kq0 = (tid >> 7);       // 0..1
    // B loader: one float4 per thread per chunk.
    const int bk  = tid >> 4;         // 0..15
    const int bn4 = (tid & 15) * 4;

    const int nkc = K / BKT;

    float4 ra0, ra1, rb;

    // ---- preload chunk 0 into registers, store to buffer 0 ----
    ra0 = *(const float4*)&A[(size_t)(mbase + ar) * lda + kq0 * 4];
    ra1 = *(const float4*)&A[(size_t)(mbase + ar) * lda + (kq0 + 2) * 4];
    rb  = *(const float4*)&B[(size_t)bk * ldb + nbase + bn4];
    {
        float* sA0 = sA;
        float* sB0 = sB;
        sA0[(kq0 * 4 + 0) * 128 + ar] = ra0.x;
        sA0[(kq0 * 4 + 1) * 128 + ar] = ra0.y;
        sA0[(kq0 * 4 + 2) * 128 + ar] = ra0.z;
        sA0[(kq0 * 4 + 3) * 128 + ar] = ra0.w;
        sA0[((kq0 + 2) * 4 + 0) * 128 + ar] = ra1.x;
        sA0[((kq0 + 2) * 4 + 1) * 128 + ar] = ra1.y;
        sA0[((kq0 + 2) * 4 + 2) * 128 + ar] = ra1.z;
        sA0[((kq0 + 2) * 4 + 3) * 128 + ar] = ra1.w;
        *(float4*)&sB0[bk * 64 + bn4] = rb;
    }
    __syncthreads();

    for (int kc = 0; kc < nkc; kc++) {
        const int cur = kc & 1;
        const float* sAc = sA + cur * (BKT * 128);
        const float* sBc = sB + cur * (BKT * 64);
        const bool more = (kc + 1 < nkc);

        // ---- issue next chunk's global loads into registers (no consumer yet) ----
        if (more) {
            const int kb = (kc + 1) * BKT;
            ra0 = *(const float4*)&A[(size_t)(mbase + ar) * lda + kb + kq0 * 4];
            ra1 = *(const float4*)&A[(size_t)(mbase + ar) * lda + kb + (kq0 + 2) * 4];
            rb  = *(const float4*)&B[(size_t)(kb + bk) * ldb + nbase + bn4];
        }

        // ---- compute on current buffer (overlaps with in-flight LDGs) ----
#pragma unroll
        for (int k = 0; k < BKT; k++) {
            float4 a0 = *(const float4*)&sAc[k * 128 + ty * 8];
            float4 a1 = *(const float4*)&sAc[k * 128 + ty * 8 + 4];
            float4 b  = *(const float4*)&sBc[k * 64 + tx * 4];
            acc[0][0] += a0.x * b.x; acc[0][1] += a0.x * b.y; acc[0][2] += a0.x * b.z; acc[0][3] += a0.x * b.w;
            acc[1][0] += a0.y * b.x; acc[1][1] += a0.y * b.y; acc[1][2] += a0.y * b.z; acc[1][3] += a0.y * b.w;
            acc[2][0] += a0.z * b.x; acc[2][1] += a0.z * b.y; acc[2][2] += a0.z * b.z; acc[2][3] += a0.z * b.w;
            acc[3][0] += a0.w * b.x; acc[3][1] += a0.w * b.y; acc[3][2] += a0.w * b.z; acc[3][3] += a0.w * b.w;
            acc[4][0] += a1.x * b.x; acc[4][1] += a1.x * b.y; acc[4][2] += a1.x * b.z; acc[4][3] += a1.x * b.w;
            acc[5][0] += a1.y * b.x; acc[5][1] += a1.y * b.y; acc[5][2] += a1.y * b.z; acc[5][3] += a1.y * b.w;
            acc[6][0] += a1.z * b.x; acc[6][1] += a1.z * b.y; acc[6][2] += a1.z * b.z; acc[6][3] += a1.z * b.w;
            acc[7][0] += a1.w * b.x; acc[7][1] += a1.w * b.y; acc[7][2] += a1.w * b.z; acc[7][3] += a1.w * b.w;
        }

        // ---- store staged registers into the other buffer, then one sync ----
        if (more) {
            float* sAn = sA + (cur ^ 1) * (BKT * 128);
            float* sBn = sB + (cur ^ 1) * (BKT * 64);
            sAn[(kq0 * 4 + 0) * 128 + ar] = ra0.x;
            sAn[(kq0 * 4 + 1) * 128 + ar] = ra0.y;
            sAn[(kq0 * 4 + 2) * 128 + ar] = ra0.z;
            sAn[(kq0 * 4 + 3) * 128 + ar] = ra0.w;
            sAn[((kq0 + 2) * 4 + 0) * 128 + ar] = ra1.x;
            sAn[((kq0 + 2) * 4 + 1) * 128 + ar] = ra1.y;
            sAn[((kq0 + 2) * 4 + 2) * 128 + ar] = ra1.z;
            sAn[((kq0 + 2) * 4 + 3) * 128 + ar] = ra1.w;
            *(float4*)&sBn[bk * 64 + bn4] = rb;
            __syncthreads();
        }
    }
}

#define GEMM_SMEM() \
    __shared__ float sA[2 * BKT * 128]; \
    __shared__ float sB[2 * BKT * 64]; \
    float acc[8][4] = {}; \
    const int tx = threadIdx.x & 15; \
    const int ty = threadIdx.x >> 4;

// ---------------- kernels ----------------
__global__ void k_init()
{
    int idx = blockIdx.x * blockDim.x + threadIdx.x;
    if (idx < BSZ * HH) { g_h[idx] = 0.0f; g_c[idx] = 0.0f; }
}

// x_proj = x @ W_x + b    (M=32768, K=512, N=4096); grid (64, 256)
__global__ void k_xproj(const float* __restrict__ x,
                        const float* __restrict__ Wx,
                        const float* __restrict__ bias)
{
    const int mbase = blockIdx.y * BMT, nbase = blockIdx.x * BNT;
    GEMM_SMEM();
    gemm_core(x, FF, Wx, G4, FF, mbase, nbase, sA, sB, acc);

    const int cc = nbase + tx * 4;
    float4 bb = *(const float4*)&bias[cc];
#pragma unroll
    for (int i = 0; i < 8; i++) {
        size_t row = (size_t)mbase + ty * 8 + i;
        float4 v = make_float4(acc[i][0] + bb.x, acc[i][1] + bb.y,
                               acc[i][2] + bb.z, acc[i][3] + bb.w);
        *(float4*)&g_xproj[row * G4 + cc] = v;
    }
}

// phase A: z0: gbuf = xp_t + h@R_h (N=4096); z1: pf = c@P_f; z2: pi = c@P_i (N=1024)
// grid (64, 2, 3)
__global__ void k_phaseA(const float* __restrict__ Rh,
                         const float* __restrict__ Pf,
                         const float* __restrict__ Pi,
                         int t)
{
    const int z = blockIdx.z;
    if (z > 0 && blockIdx.x >= 16) return;

    const int mbase = blockIdx.y * BMT, nbase = blockIdx.x * BNT;
    GEMM_SMEM();

    if (z == 0)      gemm_core(g_h, HH, Rh, G4, HH, mbase, nbase, sA, sB, acc);
    else if (z == 1) gemm_core(g_c, HH, Pf, HH, HH, mbase, nbase, sA, sB, acc);
    else             gemm_core(g_c, HH, Pi, HH, HH, mbase, nbase, sA, sB, acc);

    const int cc = nbase + tx * 4;
#pragma unroll
    for (int i = 0; i < 8; i++) {
        size_t row = (size_t)mbase + ty * 8 + i;
        if (z == 0) {
            float4 xp = *(const float4*)&g_xproj[(row * TT + t) * (size_t)G4 + cc];
            float4 v = make_float4(acc[i][0] + xp.x, acc[i][1] + xp.y,
                                   acc[i][2] + xp.z, acc[i][3] + xp.w);
            *(float4*)&g_gbuf[row * G4 + cc] = v;
        } else {
            float* outp = (z == 1) ? g_pf : g_pi;
            float4 v = make_float4(acc[i][0], acc[i][1], acc[i][2], acc[i][3]);
            *(float4*)&outp[row * HH + cc] = v;
        }
    }
}

// cell update
__global__ void k_cell()
{
    int idx = blockIdx.x * blockDim.x + threadIdx.x;
    if (idx >= BSZ * HH) return;
    int b = idx >> 10, j = idx & 1023;
    const float* gr = g_gbuf + (size_t)b * G4;
    float f = sigm(gr[j] + g_pf[idx]);
    float i = sigm(gr[HH + j] + g_pi[idx]);
    float ct = tanhf(gr[2 * HH + j]);
    g_c[idx] = g_c[idx] * f + ct * i;
}

// phase B: po = c@P_o ; h = tanh(c) * sigm(go + po) ; grid (16, 2)
__global__ void k_phaseB(const float* __restrict__ Po,
                         float* __restrict__ dout, int last)
{
    const int mbase = blockIdx.y * BMT, nbase = blockIdx.x * BNT;
    GEMM_SMEM();
    gemm_core(g_c, HH, Po, HH, HH, mbase, nbase, sA, sB, acc);

    const int cc = nbase + tx * 4;
#pragma unroll
    for (int i = 0; i < 8; i++) {
        size_t row = (size_t)mbase + ty * 8 + i;
        float4 cv = *(const float4*)&g_c[row * HH + cc];
        float4 ov = *(const float4*)&g_gbuf[row * G4 + 3 * HH + cc];
        float4 v;
        v.x = tanhf(cv.x) * sigm(ov.x + acc[i][0]);
        v.y = tanhf(cv.y) * sigm(ov.y + acc[i][1]);
        v.z = tanhf(cv.z) * sigm(ov.z + acc[i][2]);
        v.w = tanhf(cv.w) * sigm(ov.w + acc[i][3]);
        *(float4*)&g_h[row * HH + cc] = v;
        if (last) *(float4*)&dout[row * HH + cc] = v;
    }
}

// ---------------- launch ----------------
extern "C" void kernel_launch(void* const* d_in, const int* in_sizes, int n_in,
                              void* d_out, int out_size)
{
    const float* x  = (const float*)d_in[0];
    const float* Wx = (const float*)d_in[1];
    const float* b  = (const float*)d_in[2];
    const float* Rh = (const float*)d_in[3];
    const float* Pf = (const float*)d_in[4];
    const float* Pi = (const float*)d_in[5];
    const float* Po = (const float*)d_in[6];
    float* out = (float*)d_out;
    (void)in_sizes; (void)n_in; (void)out_size;

    k_init<<<(BSZ * HH + 511) / 512, 512>>>();

    k_xproj<<<dim3(G4 / BNT, (BSZ * TT) / BMT), 256>>>(x, Wx, b);

    for (int t = 0; t < TT; t++) {
        k_phaseA<<<dim3(G4 / BNT, BSZ / BMT, 3), 256>>>(Rh, Pf, Pi, t);
        k_cell<<<(BSZ * HH + 511) / 512, 512>>>();
        k_phaseB<<<dim3(HH / BNT, BSZ / BMT), 256>>>(Po, out, (t == TT - 1) ? 1 : 0);
    }
}